// round 1
// baseline (speedup 1.0000x reference)
#include <cuda_runtime.h>
#include <math.h>

#define T_ 256
#define B_ 32
#define E_ 256
#define H_ 256
#define K_ 48
#define M_ (T_*B_)      /* 8192 rows (t*B+b) */
#define G4_ 1024        /* 4*H */

// ---------------- scratch (device globals; no allocs allowed) ----------------
__device__ float g_emb [M_*E_];           // embedded input, (t*B+b, 256)
__device__ float g_xcat[M_*512];          // concat hf|hb,  (t*B+b, 512)
__device__ float g_pref[(size_t)M_*G4_];  // pre-gates fwd
__device__ float g_preb[(size_t)M_*G4_];  // pre-gates bwd
__device__ float g_emit[M_*K_];           // emit, (t*B+b, 48)
__device__ float g_h   [2*2*H_*B_];       // [buf][dir][u][b]
__device__ int   g_bar [2*2*T_];          // [layer][dir][step]
__device__ float g_part[B_];

// ---------------- init: zero h state + barriers each launch ----------------
__global__ void init_kernel(int full) {
    int tid = blockIdx.x * blockDim.x + threadIdx.x;
    int n = blockDim.x * gridDim.x;
    for (int i = tid; i < 2*2*H_*B_; i += n) g_h[i] = 0.f;
    if (full) for (int i = tid; i < 2*2*T_; i += n) g_bar[i] = 0;
}

// ---------------- embedding gather + mask output ----------------
__global__ void embed_kernel(const int* __restrict__ sentence,
                             const float* __restrict__ embed,
                             float* __restrict__ out_mask) {
    int m = blockIdx.x;             // m = t*B + b
    int t = m >> 5, b = m & 31;
    int tok = sentence[b * T_ + t];
    const float4* src = (const float4*)(embed + (size_t)tok * E_);
    float4* dst = (float4*)(g_emb + (size_t)m * E_);
    dst[threadIdx.x] = src[threadIdx.x];        // 64 threads * float4 = 256
    if (threadIdx.x == 0) out_mask[b * T_ + t] = (tok != 0) ? 1.f : 0.f;
}

// ---------------- SGEMM: C[M,1024] = A[M,Kd] @ W[1024,Kd]^T + bias ----------------
// grid(16, 64), block 256. BM=128, BN=64, BK=8, thread tile 8x4.
__global__ void gemm_pre(const float* __restrict__ A, const float* __restrict__ W,
                         const float* __restrict__ bias, float* __restrict__ C, int Kd) {
    __shared__ float As[8][128];
    __shared__ float Bs[8][64];
    int tid = threadIdx.x;
    int row0 = blockIdx.y * 128;
    int col0 = blockIdx.x * 64;
    int tr = tid >> 4, tc = tid & 15;      // 16x16 thread grid
    int ar = tid >> 1, ak = (tid & 1) * 4; // A load: 128 rows x 8k
    int wc = tid >> 2, wk = (tid & 3) * 2; // W load: 64 rows x 8k
    float acc[8][4];
#pragma unroll
    for (int i = 0; i < 8; i++)
#pragma unroll
        for (int j = 0; j < 4; j++) acc[i][j] = 0.f;

    for (int k0 = 0; k0 < Kd; k0 += 8) {
        float4 av = *(const float4*)(A + (size_t)(row0 + ar) * Kd + k0 + ak);
        float2 wv = *(const float2*)(W + (size_t)(col0 + wc) * Kd + k0 + wk);
        As[ak+0][ar] = av.x; As[ak+1][ar] = av.y; As[ak+2][ar] = av.z; As[ak+3][ar] = av.w;
        Bs[wk+0][wc] = wv.x; Bs[wk+1][wc] = wv.y;
        __syncthreads();
#pragma unroll
        for (int k = 0; k < 8; ++k) {
            float4 a0 = *(const float4*)&As[k][tr*8];
            float4 a1 = *(const float4*)&As[k][tr*8+4];
            float4 b0 = *(const float4*)&Bs[k][tc*4];
            float a[8] = {a0.x,a0.y,a0.z,a0.w,a1.x,a1.y,a1.z,a1.w};
            float bb[4] = {b0.x,b0.y,b0.z,b0.w};
#pragma unroll
            for (int i = 0; i < 8; i++)
#pragma unroll
                for (int j = 0; j < 4; j++) acc[i][j] = fmaf(a[i], bb[j], acc[i][j]);
        }
        __syncthreads();
    }
#pragma unroll
    for (int i = 0; i < 8; i++) {
        int r = row0 + tr * 8 + i;
#pragma unroll
        for (int j = 0; j < 4; j++) {
            int c = col0 + tc * 4 + j;
            C[(size_t)r * G4_ + c] = acc[i][j] + bias[c];
        }
    }
}

// ---------------- persistent BiLSTM layer ----------------
// grid 128 (dir = blk/64), block 256, dyn smem 68096B.
// block owns 4 hidden units x 32 batches; 8-warp split-K GEMM of h @ Whh^T.
__global__ void __launch_bounds__(256, 1)
lstm_layer(const float* __restrict__ pre_f, const float* __restrict__ pre_b,
           const float* __restrict__ Whh_f, const float* __restrict__ Whh_b,
           const int* __restrict__ sentence, float* __restrict__ xcat,
           int* __restrict__ bar) {
    extern __shared__ float sm[];
    float* w_sh = sm;                 // [256][16]  (k-major)
    float* h_sh = sm + 4096;          // [256][32]  (unit-major = k-major)
    float* red  = sm + 4096 + 8192;   // [8][512]
    float* gsum = red + 4096;         // [512]
    float* c_sh = gsum + 512;         // [128]

    int tid = threadIdx.x;
    int dir = blockIdx.x >> 6;
    int blk = blockIdx.x & 63;
    int u_base = blk * 4;
    const float* pre = dir ? pre_b : pre_f;
    const float* Whh = dir ? Whh_b : Whh_f;

    // load weight slice: rows r = gate*4+ui -> global row gate*256 + u_base + ui
    for (int idx = tid; idx < 16 * 256; idx += 256) {
        int r = idx >> 8, k = idx & 255;
        int gate = r >> 2, ui = r & 3;
        w_sh[k * 16 + r] = Whh[(size_t)(gate * 256 + u_base + ui) * 256 + k];
    }
    if (tid < 128) c_sh[tid] = 0.f;

    int warp = tid >> 5, lane = tid & 31;
    int li = lane >> 2, lj = lane & 3;     // batches 4*li.., rows 4*lj..
    int ub = tid >> 2, uui = tid & 3;      // update thread -> (batch, unit)
    int cur = 0;

    for (int s = 0; s < T_; ++s) {
        int t = dir ? (T_ - 1 - s) : s;
        // load full h (8192 floats) for this direction
        const float* hsrc = g_h + (cur * 2 + dir) * (H_ * B_);
#pragma unroll
        for (int i = 0; i < 8; ++i) {
            int off = (tid + i * 256) * 4;
            *(float4*)(h_sh + off) = *(const float4*)(hsrc + off);
        }
        // prefetch pre-gates + mask
        float pg0 = 0, pg1 = 0, pg2 = 0, pg3 = 0; int mvalid = 0;
        if (tid < 128) {
            const float* pp = pre + ((size_t)t * B_ + ub) * G4_ + u_base + uui;
            pg0 = pp[0]; pg1 = pp[256]; pg2 = pp[512]; pg3 = pp[768];
            mvalid = (sentence[ub * T_ + t] != 0);
        }
        __syncthreads();

        // split-K GEMM: warp handles k in [warp*32, warp*32+32)
        float acc[4][4];
#pragma unroll
        for (int i = 0; i < 4; i++)
#pragma unroll
            for (int j = 0; j < 4; j++) acc[i][j] = 0.f;
        int kbase = warp * 32;
#pragma unroll 8
        for (int kk = 0; kk < 32; ++kk) {
            int k = kbase + kk;
            float4 hv = *(const float4*)(h_sh + k * 32 + li * 4);
            float4 wv = *(const float4*)(w_sh + k * 16 + lj * 4);
            acc[0][0]=fmaf(hv.x,wv.x,acc[0][0]); acc[0][1]=fmaf(hv.x,wv.y,acc[0][1]);
            acc[0][2]=fmaf(hv.x,wv.z,acc[0][2]); acc[0][3]=fmaf(hv.x,wv.w,acc[0][3]);
            acc[1][0]=fmaf(hv.y,wv.x,acc[1][0]); acc[1][1]=fmaf(hv.y,wv.y,acc[1][1]);
            acc[1][2]=fmaf(hv.y,wv.z,acc[1][2]); acc[1][3]=fmaf(hv.y,wv.w,acc[1][3]);
            acc[2][0]=fmaf(hv.z,wv.x,acc[2][0]); acc[2][1]=fmaf(hv.z,wv.y,acc[2][1]);
            acc[2][2]=fmaf(hv.z,wv.z,acc[2][2]); acc[2][3]=fmaf(hv.z,wv.w,acc[2][3]);
            acc[3][0]=fmaf(hv.w,wv.x,acc[3][0]); acc[3][1]=fmaf(hv.w,wv.y,acc[3][1]);
            acc[3][2]=fmaf(hv.w,wv.z,acc[3][2]); acc[3][3]=fmaf(hv.w,wv.w,acc[3][3]);
        }
        float* rp = red + warp * 512;
#pragma unroll
        for (int i = 0; i < 4; i++)
            *(float4*)(rp + (li * 4 + i) * 16 + lj * 4) =
                make_float4(acc[i][0], acc[i][1], acc[i][2], acc[i][3]);
        __syncthreads();

        // reduce 8 partials -> gsum[512], 2 outputs/thread (float2)
        {
            float2 ssum = make_float2(0.f, 0.f);
#pragma unroll
            for (int w = 0; w < 8; ++w) {
                float2 v = *(const float2*)(red + w * 512 + tid * 2);
                ssum.x += v.x; ssum.y += v.y;
            }
            *(float2*)(gsum + tid * 2) = ssum;
        }
        __syncthreads();

        // cell update for 128 (b,u) pairs
        if (tid < 128) {
            float gi = gsum[ub * 16 + 0 + uui] + pg0;
            float gf = gsum[ub * 16 + 4 + uui] + pg1;
            float gg = gsum[ub * 16 + 8 + uui] + pg2;
            float go = gsum[ub * 16 + 12 + uui] + pg3;
            float c  = c_sh[tid];
            float si = 1.f / (1.f + expf(-gi));
            float sf = 1.f / (1.f + expf(-gf));
            float so = 1.f / (1.f + expf(-go));
            float c2 = sf * c + si * tanhf(gg);
            float h2 = so * tanhf(c2);
            float hold = h_sh[(u_base + uui) * 32 + ub];
            float hw, ow;
            if (mvalid) { c_sh[tid] = c2; hw = h2; ow = h2; }
            else        { hw = hold; ow = 0.f; }
            g_h[((cur ^ 1) * 2 + dir) * (H_ * B_) + (u_base + uui) * 32 + ub] = hw;
            xcat[((size_t)t * B_ + ub) * 512 + dir * 256 + u_base + uui] = ow;
        }

        // per-direction grid barrier for this step
        __threadfence();
        __syncthreads();
        if (tid == 0) {
            int* p = bar + dir * T_ + s;
            atomicAdd(p, 1);
            volatile int* vp = p;
            while (*vp < 64) { __nanosleep(64); }
            __threadfence();
        }
        __syncthreads();
        cur ^= 1;
    }
}

// ---------------- emit: (8192x512) @ Wout^T(48x512) + bout ----------------
// grid 256, block 256. Also writes transposed output emit (B,T,K).
__global__ void emit_kernel(const float* __restrict__ xcat, const float* __restrict__ Wout,
                            const float* __restrict__ bout, float* __restrict__ emit,
                            float* __restrict__ out_emit) {
    int tid = threadIdx.x;
    int r = tid & 31;
    int cg = tid >> 5;                 // 8 groups x 6 cols
    int m = blockIdx.x * 32 + r;
    int t = m >> 5, b = m & 31;
    const float4* A = (const float4*)(xcat + (size_t)m * 512);
    float acc[6] = {0, 0, 0, 0, 0, 0};
    for (int k4 = 0; k4 < 128; ++k4) {
        float4 a = __ldg(A + k4);
#pragma unroll
        for (int j = 0; j < 6; ++j) {
            int col = cg * 6 + j;
            float4 w = __ldg((const float4*)(Wout + (size_t)col * 512) + k4);
            acc[j] += a.x * w.x + a.y * w.y + a.z * w.z + a.w * w.w;
        }
    }
#pragma unroll
    for (int j = 0; j < 6; ++j) {
        int col = cg * 6 + j;
        float v = acc[j] + bout[col];
        emit[(size_t)m * K_ + col] = v;
        out_emit[((size_t)b * T_ + t) * K_ + col] = v;
    }
}

// ---------------- CRF per batch: numerator + forward algorithm ----------------
__global__ void crf_kernel(const float* __restrict__ emit, const int* __restrict__ tags,
                           const int* __restrict__ lengths, const float* __restrict__ start_t,
                           const float* __restrict__ end_t, const float* __restrict__ trans,
                           float* __restrict__ part) {
    __shared__ float tr_sh[K_ * K_];
    __shared__ float sc[2][K_];
    __shared__ float red[64];
    int b = blockIdx.x, tid = threadIdx.x;
    for (int i = tid; i < K_ * K_; i += 64) tr_sh[i] = trans[i];
    int len = lengths[b];
    if (tid < K_) sc[0][tid] = start_t[tid] + emit[(size_t)b * K_ + tid];
    __syncthreads();
    int curb = 0;
    for (int t = 1; t < len; ++t) {
        if (tid < K_) {
            int k = tid;
            float mx = -1e30f;
            for (int j = 0; j < K_; ++j)
                mx = fmaxf(mx, sc[curb][j] + tr_sh[j * K_ + k]);
            float ss = 0.f;
            for (int j = 0; j < K_; ++j)
                ss += expf(sc[curb][j] + tr_sh[j * K_ + k] - mx);
            sc[curb ^ 1][k] = mx + logf(ss) + emit[((size_t)t * B_ + b) * K_ + k];
        }
        __syncthreads();
        curb ^= 1;
    }
    // numerator (pure sum over t, parallel)
    float np = 0.f;
    for (int t = tid; t < len; t += 64) {
        int tg = tags[b * T_ + t];
        float e = emit[((size_t)t * B_ + b) * K_ + tg];
        if (t == 0) np += start_t[tg] + e;
        else        np += tr_sh[tags[b * T_ + t - 1] * K_ + tg] + e;
        if (t == len - 1) np += end_t[tg];
    }
    red[tid] = np;
    __syncthreads();
    if (tid == 0) {
        float num = 0.f;
        for (int i = 0; i < 64; ++i) num += red[i];
        float mx = -1e30f;
        for (int k = 0; k < K_; ++k) mx = fmaxf(mx, sc[curb][k] + end_t[k]);
        float ss = 0.f;
        for (int k = 0; k < K_; ++k) ss += expf(sc[curb][k] + end_t[k] - mx);
        float den = mx + logf(ss);
        part[b] = num - den;
    }
}

__global__ void finalize_kernel(float* __restrict__ out_loss) {
    if (threadIdx.x == 0) {
        float s = 0.f;
        for (int i = 0; i < B_; ++i) s += g_part[i];
        out_loss[0] = s / (float)B_;
    }
}

// ---------------- host launcher ----------------
extern "C" void kernel_launch(void* const* d_in, const int* in_sizes, int n_in,
                              void* d_out, int out_size) {
    const int*   sentence = (const int*)d_in[0];
    const int*   lengths  = (const int*)d_in[1];
    const int*   tags     = (const int*)d_in[2];
    const float* embed    = (const float*)d_in[3];
    const float* Wih_0f = (const float*)d_in[4];
    const float* Whh_0f = (const float*)d_in[5];
    const float* b_0f   = (const float*)d_in[6];
    const float* Wih_0b = (const float*)d_in[7];
    const float* Whh_0b = (const float*)d_in[8];
    const float* b_0b   = (const float*)d_in[9];
    const float* Wih_1f = (const float*)d_in[10];
    const float* Whh_1f = (const float*)d_in[11];
    const float* b_1f   = (const float*)d_in[12];
    const float* Wih_1b = (const float*)d_in[13];
    const float* Whh_1b = (const float*)d_in[14];
    const float* b_1b   = (const float*)d_in[15];
    const float* Wout   = (const float*)d_in[16];
    const float* bout   = (const float*)d_in[17];
    const float* start_t = (const float*)d_in[18];
    const float* end_t   = (const float*)d_in[19];
    const float* trans   = (const float*)d_in[20];

    float* out = (float*)d_out;
    float* out_emit = out;                       // (B,T,K) = 393216
    float* out_loss = out + (size_t)B_ * T_ * K_;
    float* out_mask = out_loss + 1;              // (B,T)

    const int LSTM_SMEM = 17024 * 4;             // 68096 B
    cudaFuncSetAttribute(lstm_layer, cudaFuncAttributeMaxDynamicSharedMemorySize, LSTM_SMEM);

    float *pre_f, *pre_b, *xcat, *emb, *emit;
    cudaGetSymbolAddress((void**)&pre_f, g_pref);
    cudaGetSymbolAddress((void**)&pre_b, g_preb);
    cudaGetSymbolAddress((void**)&xcat,  g_xcat);
    cudaGetSymbolAddress((void**)&emb,   g_emb);
    cudaGetSymbolAddress((void**)&emit,  g_emit);
    int* barp; cudaGetSymbolAddress((void**)&barp, g_bar);
    float* partp; cudaGetSymbolAddress((void**)&partp, g_part);

    dim3 ggrid(16, 64);

    init_kernel<<<32, 256>>>(1);
    embed_kernel<<<M_, 64>>>(sentence, embed, out_mask);

    gemm_pre<<<ggrid, 256>>>(emb, Wih_0f, b_0f, pre_f, E_);
    gemm_pre<<<ggrid, 256>>>(emb, Wih_0b, b_0b, pre_b, E_);
    lstm_layer<<<128, 256, LSTM_SMEM>>>(pre_f, pre_b, Whh_0f, Whh_0b, sentence, xcat, barp);

    gemm_pre<<<ggrid, 256>>>(xcat, Wih_1f, b_1f, pre_f, 512);
    gemm_pre<<<ggrid, 256>>>(xcat, Wih_1b, b_1b, pre_b, 512);
    init_kernel<<<32, 256>>>(0);   // re-zero h state for layer 1
    lstm_layer<<<128, 256, LSTM_SMEM>>>(pre_f, pre_b, Whh_1f, Whh_1b, sentence, xcat, barp + 2 * T_);

    emit_kernel<<<M_ / 32, 256>>>(xcat, Wout, bout, emit, out_emit);
    crf_kernel<<<B_, 64>>>(emit, tags, lengths, start_t, end_t, trans, partp);
    finalize_kernel<<<1, 32>>>(out_loss);
    (void)in_sizes; (void)n_in; (void)out_size;
}

// round 2
// speedup vs baseline: 1.1111x; 1.1111x over previous
#include <cuda_runtime.h>
#include <math.h>

#define T_ 256
#define B_ 32
#define E_ 256
#define H_ 256
#define K_ 48
#define M_ (T_*B_)      /* 8192 rows (t*B+b) */
#define G4_ 1024        /* 4*H */

typedef unsigned long long ull;

// ---------------- f32x2 packed helpers (FFMA2 path, sm_100+) ----------------
__device__ __forceinline__ ull ffma2(ull a, ull b, ull c) {
    ull d; asm("fma.rn.f32x2 %0, %1, %2, %3;" : "=l"(d) : "l"(a), "l"(b), "l"(c)); return d;
}
__device__ __forceinline__ ull add2(ull a, ull b) {
    ull d; asm("add.rn.f32x2 %0, %1, %2;" : "=l"(d) : "l"(a), "l"(b)); return d;
}
__device__ __forceinline__ ull pk2(float lo, float hi) {
    ull r; asm("mov.b64 %0, {%1, %2};" : "=l"(r) : "f"(lo), "f"(hi)); return r;
}
__device__ __forceinline__ void upk2(ull v, float& lo, float& hi) {
    asm("mov.b64 {%0, %1}, %2;" : "=f"(lo), "=f"(hi) : "l"(v));
}

// ---------------- scratch (device globals; no allocs allowed) ----------------
__device__ float g_emb [M_*E_];           // embedded input, (t*B+b, 256)
__device__ float g_xcat[M_*512];          // concat hf|hb,  (t*B+b, 512)
__device__ float g_pref[(size_t)M_*G4_];  // pre-gates fwd
__device__ float g_preb[(size_t)M_*G4_];  // pre-gates bwd
__device__ float g_emit[M_*K_];           // emit, (t*B+b, 48)
__device__ float g_h   [2*2*H_*B_];       // [buf][dir][u][b]
__device__ int   g_bar [2*2*T_];          // [layer][dir][step]
__device__ float g_part[B_];

// ---------------- init: zero h state + barriers each launch ----------------
__global__ void init_kernel(int full) {
    int tid = blockIdx.x * blockDim.x + threadIdx.x;
    int n = blockDim.x * gridDim.x;
    for (int i = tid; i < 2*2*H_*B_; i += n) g_h[i] = 0.f;
    if (full) for (int i = tid; i < 2*2*T_; i += n) g_bar[i] = 0;
}

// ---------------- embedding gather + mask output ----------------
__global__ void embed_kernel(const int* __restrict__ sentence,
                             const float* __restrict__ embed,
                             float* __restrict__ out_mask) {
    int m = blockIdx.x;             // m = t*B + b
    int t = m >> 5, b = m & 31;
    int tok = sentence[b * T_ + t];
    const float4* src = (const float4*)(embed + (size_t)tok * E_);
    float4* dst = (float4*)(g_emb + (size_t)m * E_);
    dst[threadIdx.x] = src[threadIdx.x];        // 64 threads * float4 = 256
    if (threadIdx.x == 0) out_mask[b * T_ + t] = (tok != 0) ? 1.f : 0.f;
}

// ---------------- SGEMM (FFMA2): C[M,1024] = A[M,Kd] @ W[1024,Kd]^T + bias ---
// grid(16, 64, 2), block 256. BM=128, BN=64, BK=8, thread tile 8x4.
// z-dim selects forward/backward weight set (fused launch for better waves).
__global__ void gemm_pre(const float* __restrict__ A,
                         const float* __restrict__ Wf, const float* __restrict__ Wb,
                         const float* __restrict__ biasf, const float* __restrict__ biasb,
                         float* __restrict__ Cf, float* __restrict__ Cb, int Kd) {
    __shared__ float As[8][128];
    __shared__ float Bs[8][64];
    const float* W    = blockIdx.z ? Wb : Wf;
    const float* bias = blockIdx.z ? biasb : biasf;
    float*       C    = blockIdx.z ? Cb : Cf;

    int tid = threadIdx.x;
    int row0 = blockIdx.y * 128;
    int col0 = blockIdx.x * 64;
    int tr = tid >> 4, tc = tid & 15;      // 16x16 thread grid
    int ar = tid >> 1, ak = (tid & 1) * 4; // A load: 128 rows x 8k
    int wc = tid >> 2, wk = (tid & 3) * 2; // W load: 64 rows x 8k
    ull acc2[4][4];                        // [row-pair][col]
#pragma unroll
    for (int p = 0; p < 4; p++)
#pragma unroll
        for (int j = 0; j < 4; j++) acc2[p][j] = 0ull;

    for (int k0 = 0; k0 < Kd; k0 += 8) {
        float4 av = *(const float4*)(A + (size_t)(row0 + ar) * Kd + k0 + ak);
        float2 wv = *(const float2*)(W + (size_t)(col0 + wc) * Kd + k0 + wk);
        As[ak+0][ar] = av.x; As[ak+1][ar] = av.y; As[ak+2][ar] = av.z; As[ak+3][ar] = av.w;
        Bs[wk+0][wc] = wv.x; Bs[wk+1][wc] = wv.y;
        __syncthreads();
#pragma unroll
        for (int k = 0; k < 8; ++k) {
            ulonglong2 a01 = *(const ulonglong2*)&As[k][tr*8];     // row pairs (0,1),(2,3)
            ulonglong2 a23 = *(const ulonglong2*)&As[k][tr*8+4];   // (4,5),(6,7)
            float4 b4 = *(const float4*)&Bs[k][tc*4];
            ull bd0 = pk2(b4.x, b4.x), bd1 = pk2(b4.y, b4.y);
            ull bd2 = pk2(b4.z, b4.z), bd3 = pk2(b4.w, b4.w);
            acc2[0][0]=ffma2(a01.x,bd0,acc2[0][0]); acc2[0][1]=ffma2(a01.x,bd1,acc2[0][1]);
            acc2[0][2]=ffma2(a01.x,bd2,acc2[0][2]); acc2[0][3]=ffma2(a01.x,bd3,acc2[0][3]);
            acc2[1][0]=ffma2(a01.y,bd0,acc2[1][0]); acc2[1][1]=ffma2(a01.y,bd1,acc2[1][1]);
            acc2[1][2]=ffma2(a01.y,bd2,acc2[1][2]); acc2[1][3]=ffma2(a01.y,bd3,acc2[1][3]);
            acc2[2][0]=ffma2(a23.x,bd0,acc2[2][0]); acc2[2][1]=ffma2(a23.x,bd1,acc2[2][1]);
            acc2[2][2]=ffma2(a23.x,bd2,acc2[2][2]); acc2[2][3]=ffma2(a23.x,bd3,acc2[2][3]);
            acc2[3][0]=ffma2(a23.y,bd0,acc2[3][0]); acc2[3][1]=ffma2(a23.y,bd1,acc2[3][1]);
            acc2[3][2]=ffma2(a23.y,bd2,acc2[3][2]); acc2[3][3]=ffma2(a23.y,bd3,acc2[3][3]);
        }
        __syncthreads();
    }
#pragma unroll
    for (int p = 0; p < 4; p++) {
        int r0 = row0 + tr * 8 + 2 * p;
#pragma unroll
        for (int j = 0; j < 4; j++) {
            int c = col0 + tc * 4 + j;
            float lo, hi; upk2(acc2[p][j], lo, hi);
            float bv = bias[c];
            C[(size_t)r0 * G4_ + c]       = lo + bv;
            C[(size_t)(r0+1) * G4_ + c]   = hi + bv;
        }
    }
}

// ---------------- persistent BiLSTM layer ----------------
// grid 128 (dir = blk/64), block 256, dyn smem 68096B.
// block owns 4 hidden units x 32 batches; 8-warp split-K FFMA2 GEMM of h @ Whh^T.
__global__ void __launch_bounds__(256, 1)
lstm_layer(const float* __restrict__ pre_f, const float* __restrict__ pre_b,
           const float* __restrict__ Whh_f, const float* __restrict__ Whh_b,
           const int* __restrict__ lengths, float* __restrict__ xcat,
           int* __restrict__ bar) {
    extern __shared__ float sm[];
    float* w_sh = sm;                 // [256][16]  (k-major)
    float* h_sh = sm + 4096;          // [256][32]  (unit-major = k-major)
    float* red  = sm + 4096 + 8192;   // [8][512]   (viewed as ull [8][256])
    float* gsum = red + 4096;         // [512]      (viewed as ull [256])
    float* c_sh = gsum + 512;         // [128]
    ull* red_u  = (ull*)red;
    ull* gsum_u = (ull*)gsum;

    int tid = threadIdx.x;
    int dir = blockIdx.x >> 6;
    int blk = blockIdx.x & 63;
    int u_base = blk * 4;
    const float* pre = dir ? pre_b : pre_f;
    const float* Whh = dir ? Whh_b : Whh_f;

    // load weight slice: rows r = gate*4+ui -> global row gate*256 + u_base + ui
    for (int idx = tid; idx < 16 * 256; idx += 256) {
        int r = idx >> 8, k = idx & 255;
        int gate = r >> 2, ui = r & 3;
        w_sh[k * 16 + r] = Whh[(size_t)(gate * 256 + u_base + ui) * 256 + k];
    }
    if (tid < 128) c_sh[tid] = 0.f;

    int warp = tid >> 5, lane = tid & 31;
    int li = lane >> 2, lj = lane & 3;     // batches 4*li.., rows 4*lj..
    int kbase = warp * 32;
    int ub = tid >> 2, uui = tid & 3;      // update thread -> (batch, unit)
    int cur = 0;
    int* bar_dir = bar + dir * T_;

    // prefetch pre-gates + mask (register pipeline)
    float pg0 = 0, pg1 = 0, pg2 = 0, pg3 = 0;
    float pgn0 = 0, pgn1 = 0, pgn2 = 0, pgn3 = 0;
    int len = 0;
    if (tid < 128) {
        len = lengths[ub];
        int t0 = dir ? (T_ - 1) : 0;
        const float* pp = pre + ((size_t)t0 * B_ + ub) * G4_ + u_base + uui;
        pg0 = __ldg(pp); pg1 = __ldg(pp + 256); pg2 = __ldg(pp + 512); pg3 = __ldg(pp + 768);
    }
    __syncthreads();   // w_sh / c_sh ready

    for (int s = 0; s < T_; ++s) {
        int t = dir ? (T_ - 1 - s) : s;

        // per-warp h slice load (this warp only consumes k in [kbase, kbase+32))
        {
            const float* hsrc = g_h + (cur * 2 + dir) * (H_ * B_) + kbase * 32;
            float* hdst = h_sh + kbase * 32;
#pragma unroll
            for (int i = 0; i < 8; ++i) {
                int off = (lane + i * 32) * 4;
                float4 v = __ldcg((const float4*)(hsrc + off));
                *(float4*)(hdst + off) = v;
            }
            __syncwarp();
        }

        // split-K FFMA2 GEMM: warp handles k in [kbase, kbase+32)
        ull acc2[4][2];   // [batch i][row-pair jp]
#pragma unroll
        for (int i = 0; i < 4; i++) { acc2[i][0] = 0ull; acc2[i][1] = 0ull; }
#pragma unroll 8
        for (int kk = 0; kk < 32; ++kk) {
            int k = kbase + kk;
            float4 hv = *(const float4*)(h_sh + k * 32 + li * 4);
            ulonglong2 wp = *(const ulonglong2*)(w_sh + k * 16 + lj * 4);
            ull hd0 = pk2(hv.x, hv.x), hd1 = pk2(hv.y, hv.y);
            ull hd2 = pk2(hv.z, hv.z), hd3 = pk2(hv.w, hv.w);
            acc2[0][0]=ffma2(hd0,wp.x,acc2[0][0]); acc2[0][1]=ffma2(hd0,wp.y,acc2[0][1]);
            acc2[1][0]=ffma2(hd1,wp.x,acc2[1][0]); acc2[1][1]=ffma2(hd1,wp.y,acc2[1][1]);
            acc2[2][0]=ffma2(hd2,wp.x,acc2[2][0]); acc2[2][1]=ffma2(hd2,wp.y,acc2[2][1]);
            acc2[3][0]=ffma2(hd3,wp.x,acc2[3][0]); acc2[3][1]=ffma2(hd3,wp.y,acc2[3][1]);
        }
        {
            ull* rpu = red_u + warp * 256;
#pragma unroll
            for (int i = 0; i < 4; i++) {
                rpu[(li * 4 + i) * 8 + lj * 2 + 0] = acc2[i][0];
                rpu[(li * 4 + i) * 8 + lj * 2 + 1] = acc2[i][1];
            }
        }
        __syncthreads();

        // reduce 8 partials -> gsum (one ull = row pair per thread)
        {
            ull sacc = red_u[tid];
#pragma unroll
            for (int w = 1; w < 8; ++w) sacc = add2(sacc, red_u[w * 256 + tid]);
            gsum_u[tid] = sacc;
        }
        __syncthreads();

        // cell update for 128 (b,u) pairs
        if (tid < 128) {
            float gi = gsum[ub * 16 + 0  + uui] + pg0;
            float gf = gsum[ub * 16 + 4  + uui] + pg1;
            float gg = gsum[ub * 16 + 8  + uui] + pg2;
            float go = gsum[ub * 16 + 12 + uui] + pg3;
            float c  = c_sh[tid];
            float si = 1.f / (1.f + __expf(-gi));
            float sf = 1.f / (1.f + __expf(-gf));
            float so = 1.f / (1.f + __expf(-go));
            float c2 = sf * c + si * tanhf(gg);
            float h2 = so * tanhf(c2);
            float hold = h_sh[(u_base + uui) * 32 + ub];
            int mvalid = (t < len);
            float hw, ow;
            if (mvalid) { c_sh[tid] = c2; hw = h2; ow = h2; }
            else        { hw = hold; ow = 0.f; }
            g_h[((cur ^ 1) * 2 + dir) * (H_ * B_) + (u_base + uui) * 32 + ub] = hw;
            xcat[((size_t)t * B_ + ub) * 512 + dir * 256 + u_base + uui] = ow;

            // prefetch next step's pre-gates (consumed after next barrier+gemm)
            if (s + 1 < T_) {
                int tn = dir ? (T_ - 2 - s) : (s + 1);
                const float* pp = pre + ((size_t)tn * B_ + ub) * G4_ + u_base + uui;
                pgn0 = __ldg(pp); pgn1 = __ldg(pp + 256);
                pgn2 = __ldg(pp + 512); pgn3 = __ldg(pp + 768);
            }
        }

        // per-direction grid barrier for this step
        __threadfence();
        __syncthreads();
        if (tid == 0) {
            int* p = bar_dir + s;
            atomicAdd(p, 1);
            volatile int* vp = p;
            while (*vp < 64) { }
            __threadfence();
        }
        __syncthreads();
        pg0 = pgn0; pg1 = pgn1; pg2 = pgn2; pg3 = pgn3;
        cur ^= 1;
    }
}

// ---------------- emit: (8192x512) @ Wout^T(48x512) + bout ----------------
// grid 256, block 256. Also writes transposed output emit (B,T,K).
__global__ void emit_kernel(const float* __restrict__ xcat, const float* __restrict__ Wout,
                            const float* __restrict__ bout, float* __restrict__ emit,
                            float* __restrict__ out_emit) {
    int tid = threadIdx.x;
    int r = tid & 31;
    int cg = tid >> 5;                 // 8 groups x 6 cols
    int m = blockIdx.x * 32 + r;
    int t = m >> 5, b = m & 31;
    const ulonglong2* A = (const ulonglong2*)(xcat + (size_t)m * 512);
    ull accA[6], accB[6];
#pragma unroll
    for (int j = 0; j < 6; ++j) { accA[j] = 0ull; accB[j] = 0ull; }
    for (int k4 = 0; k4 < 128; ++k4) {
        ulonglong2 a = A[k4];
#pragma unroll
        for (int j = 0; j < 6; ++j) {
            int col = cg * 6 + j;
            ulonglong2 w = ((const ulonglong2*)(Wout + (size_t)col * 512))[k4];
            accA[j] = ffma2(a.x, w.x, accA[j]);
            accB[j] = ffma2(a.y, w.y, accB[j]);
        }
    }
#pragma unroll
    for (int j = 0; j < 6; ++j) {
        int col = cg * 6 + j;
        float a0, a1, b0, b1;
        upk2(accA[j], a0, a1); upk2(accB[j], b0, b1);
        float v = a0 + a1 + b0 + b1 + bout[col];
        emit[(size_t)m * K_ + col] = v;
        out_emit[((size_t)b * T_ + t) * K_ + col] = v;
    }
}

// ---------------- CRF per batch: numerator + forward algorithm ----------------
// 192 threads: 4-way split over the j (previous-tag) dimension.
__global__ void crf_kernel(const float* __restrict__ emit, const int* __restrict__ tags,
                           const int* __restrict__ lengths, const float* __restrict__ start_t,
                           const float* __restrict__ end_t, const float* __restrict__ trans,
                           float* __restrict__ part) {
    __shared__ float tr_sh[K_ * K_];
    __shared__ float sc[K_];
    __shared__ float pmax[4][K_];
    __shared__ float psum[4][K_];
    __shared__ float redn[192];
    int b = blockIdx.x, tid = threadIdx.x;
    int k = tid % K_, jj = tid / K_;     // jj in 0..3
    for (int i = tid; i < K_ * K_; i += 192) tr_sh[i] = trans[i];
    int len = lengths[b];
    if (tid < K_) sc[tid] = start_t[tid] + emit[(size_t)b * K_ + tid];
    __syncthreads();
    for (int t = 1; t < len; ++t) {
        float v[12];
        float mx = -1e30f;
#pragma unroll
        for (int jx = 0; jx < 12; ++jx) {
            int j = jj * 12 + jx;
            v[jx] = sc[j] + tr_sh[j * K_ + k];
            mx = fmaxf(mx, v[jx]);
        }
        float ss = 0.f;
#pragma unroll
        for (int jx = 0; jx < 12; ++jx) ss += __expf(v[jx] - mx);
        pmax[jj][k] = mx; psum[jj][k] = ss;
        __syncthreads();
        if (jj == 0) {
            float m0 = pmax[0][k], m1 = pmax[1][k], m2 = pmax[2][k], m3 = pmax[3][k];
            float gm = fmaxf(fmaxf(m0, m1), fmaxf(m2, m3));
            float s = psum[0][k] * __expf(m0 - gm) + psum[1][k] * __expf(m1 - gm)
                    + psum[2][k] * __expf(m2 - gm) + psum[3][k] * __expf(m3 - gm);
            sc[k] = gm + __logf(s) + emit[((size_t)t * B_ + b) * K_ + k];
        }
        __syncthreads();
    }
    // numerator (pure sum over t, parallel)
    float np = 0.f;
    for (int t = tid; t < len; t += 192) {
        int tg = tags[b * T_ + t];
        float e = emit[((size_t)t * B_ + b) * K_ + tg];
        if (t == 0) np += start_t[tg] + e;
        else        np += tr_sh[tags[b * T_ + t - 1] * K_ + tg] + e;
        if (t == len - 1) np += end_t[tg];
    }
    redn[tid] = np;
    __syncthreads();
    if (tid == 0) {
        float num = 0.f;
        for (int i = 0; i < 192; ++i) num += redn[i];
        float mx = -1e30f;
        for (int kk = 0; kk < K_; ++kk) mx = fmaxf(mx, sc[kk] + end_t[kk]);
        float ss = 0.f;
        for (int kk = 0; kk < K_; ++kk) ss += __expf(sc[kk] + end_t[kk] - mx);
        float den = mx + __logf(ss);
        part[b] = num - den;
    }
}

__global__ void finalize_kernel(float* __restrict__ out_loss) {
    if (threadIdx.x == 0) {
        float s = 0.f;
        for (int i = 0; i < B_; ++i) s += g_part[i];
        out_loss[0] = s / (float)B_;
    }
}

// ---------------- host launcher ----------------
extern "C" void kernel_launch(void* const* d_in, const int* in_sizes, int n_in,
                              void* d_out, int out_size) {
    const int*   sentence = (const int*)d_in[0];
    const int*   lengths  = (const int*)d_in[1];
    const int*   tags     = (const int*)d_in[2];
    const float* embed    = (const float*)d_in[3];
    const float* Wih_0f = (const float*)d_in[4];
    const float* Whh_0f = (const float*)d_in[5];
    const float* b_0f   = (const float*)d_in[6];
    const float* Wih_0b = (const float*)d_in[7];
    const float* Whh_0b = (const float*)d_in[8];
    const float* b_0b   = (const float*)d_in[9];
    const float* Wih_1f = (const float*)d_in[10];
    const float* Whh_1f = (const float*)d_in[11];
    const float* b_1f   = (const float*)d_in[12];
    const float* Wih_1b = (const float*)d_in[13];
    const float* Whh_1b = (const float*)d_in[14];
    const float* b_1b   = (const float*)d_in[15];
    const float* Wout   = (const float*)d_in[16];
    const float* bout   = (const float*)d_in[17];
    const float* start_t = (const float*)d_in[18];
    const float* end_t   = (const float*)d_in[19];
    const float* trans   = (const float*)d_in[20];

    float* out = (float*)d_out;
    float* out_emit = out;                       // (B,T,K) = 393216
    float* out_loss = out + (size_t)B_ * T_ * K_;
    float* out_mask = out_loss + 1;              // (B,T)

    const int LSTM_SMEM = 17024 * 4;             // 68096 B
    cudaFuncSetAttribute(lstm_layer, cudaFuncAttributeMaxDynamicSharedMemorySize, LSTM_SMEM);

    float *pre_f, *pre_b, *xcat, *emb, *emit;
    cudaGetSymbolAddress((void**)&pre_f, g_pref);
    cudaGetSymbolAddress((void**)&pre_b, g_preb);
    cudaGetSymbolAddress((void**)&xcat,  g_xcat);
    cudaGetSymbolAddress((void**)&emb,   g_emb);
    cudaGetSymbolAddress((void**)&emit,  g_emit);
    int* barp; cudaGetSymbolAddress((void**)&barp, g_bar);
    float* partp; cudaGetSymbolAddress((void**)&partp, g_part);

    dim3 ggrid(16, 64, 2);

    init_kernel<<<32, 256>>>(1);
    embed_kernel<<<M_, 64>>>(sentence, embed, out_mask);

    gemm_pre<<<ggrid, 256>>>(emb, Wih_0f, Wih_0b, b_0f, b_0b, pre_f, pre_b, E_);
    lstm_layer<<<128, 256, LSTM_SMEM>>>(pre_f, pre_b, Whh_0f, Whh_0b, lengths, xcat, barp);

    gemm_pre<<<ggrid, 256>>>(xcat, Wih_1f, Wih_1b, b_1f, b_1b, pre_f, pre_b, 512);
    init_kernel<<<32, 256>>>(0);   // re-zero h state for layer 1
    lstm_layer<<<128, 256, LSTM_SMEM>>>(pre_f, pre_b, Whh_1f, Whh_1b, lengths, xcat, barp + 2 * T_);

    emit_kernel<<<M_ / 32, 256>>>(xcat, Wout, bout, emit, out_emit);
    crf_kernel<<<B_, 192>>>(emit, tags, lengths, start_t, end_t, trans, partp);
    finalize_kernel<<<1, 32>>>(out_loss);
    (void)in_sizes; (void)n_in; (void)out_size;
}

// round 5
// speedup vs baseline: 1.1542x; 1.0388x over previous
#include <cuda_runtime.h>
#include <math.h>

#define T_ 256
#define B_ 32
#define E_ 256
#define H_ 256
#define K_ 48
#define M_ (T_*B_)      /* 8192 rows (t*B+b) */
#define G4_ 1024        /* 4*H */

typedef unsigned long long ull;

// ---------------- f32x2 packed helpers (FFMA2 path, sm_100+) ----------------
__device__ __forceinline__ ull ffma2(ull a, ull b, ull c) {
    ull d; asm("fma.rn.f32x2 %0, %1, %2, %3;" : "=l"(d) : "l"(a), "l"(b), "l"(c)); return d;
}
__device__ __forceinline__ ull add2(ull a, ull b) {
    ull d; asm("add.rn.f32x2 %0, %1, %2;" : "=l"(d) : "l"(a), "l"(b)); return d;
}
__device__ __forceinline__ ull pk2(float lo, float hi) {
    ull r; asm("mov.b64 %0, {%1, %2};" : "=l"(r) : "f"(lo), "f"(hi)); return r;
}
__device__ __forceinline__ void upk2(ull v, float& lo, float& hi) {
    asm("mov.b64 {%0, %1}, %2;" : "=f"(lo), "=f"(hi) : "l"(v));
}

// ---------------- scratch (device globals; no allocs allowed) ----------------
__device__ float g_emb [M_*E_];           // embedded input, (t*B+b, 256)
__device__ float g_xcat[M_*512];          // concat hf|hb,  (t*B+b, 512)
__device__ float g_pref[(size_t)M_*G4_];  // pre-gates fwd
__device__ float g_preb[(size_t)M_*G4_];  // pre-gates bwd
__device__ float g_emit[M_*K_];           // emit, (t*B+b, 48)
__device__ float g_h   [2*2*2*H_*B_];     // [layer][buf][dir][u*32+b]
__device__ int   g_bar [2*2*T_];          // [layer][dir][step]
__device__ float g_part[B_];

// ---------------- init: zero h state + barriers each launch ----------------
__global__ void init_kernel() {
    int tid = blockIdx.x * blockDim.x + threadIdx.x;
    int n = blockDim.x * gridDim.x;
    for (int i = tid; i < 2*2*2*H_*B_; i += n) g_h[i] = 0.f;
    for (int i = tid; i < 2*2*T_; i += n) g_bar[i] = 0;
}

// ---------------- embedding gather + mask output ----------------
__global__ void embed_kernel(const int* __restrict__ sentence,
                             const float* __restrict__ embed,
                             float* __restrict__ out_mask) {
    int m = blockIdx.x;             // m = t*B + b
    int t = m >> 5, b = m & 31;
    int tok = sentence[b * T_ + t];
    const float4* src = (const float4*)(embed + (size_t)tok * E_);
    float4* dst = (float4*)(g_emb + (size_t)m * E_);
    dst[threadIdx.x] = src[threadIdx.x];        // 64 threads * float4 = 256
    if (threadIdx.x == 0) out_mask[b * T_ + t] = (tok != 0) ? 1.f : 0.f;
}

// ---------------- SGEMM (FFMA2): C[M,1024] = A[M,Kd] @ W[1024,Kd]^T + bias ---
// grid(16, 64, 2), block 256. BM=128, BN=64, BK=8, thread tile 8x4.
__global__ void gemm_pre(const float* __restrict__ A,
                         const float* __restrict__ Wf, const float* __restrict__ Wb,
                         const float* __restrict__ biasf, const float* __restrict__ biasb,
                         float* __restrict__ Cf, float* __restrict__ Cb, int Kd) {
    __shared__ float As[8][128];
    __shared__ float Bs[8][64];
    const float* W    = blockIdx.z ? Wb : Wf;
    const float* bias = blockIdx.z ? biasb : biasf;
    float*       C    = blockIdx.z ? Cb : Cf;

    int tid = threadIdx.x;
    int row0 = blockIdx.y * 128;
    int col0 = blockIdx.x * 64;
    int tr = tid >> 4, tc = tid & 15;      // 16x16 thread grid
    int ar = tid >> 1, ak = (tid & 1) * 4; // A load: 128 rows x 8k
    int wc = tid >> 2, wk = (tid & 3) * 2; // W load: 64 rows x 8k
    ull acc2[4][4];                        // [row-pair][col]
#pragma unroll
    for (int p = 0; p < 4; p++)
#pragma unroll
        for (int j = 0; j < 4; j++) acc2[p][j] = 0ull;

    for (int k0 = 0; k0 < Kd; k0 += 8) {
        float4 av = *(const float4*)(A + (size_t)(row0 + ar) * Kd + k0 + ak);
        float2 wv = *(const float2*)(W + (size_t)(col0 + wc) * Kd + k0 + wk);
        As[ak+0][ar] = av.x; As[ak+1][ar] = av.y; As[ak+2][ar] = av.z; As[ak+3][ar] = av.w;
        Bs[wk+0][wc] = wv.x; Bs[wk+1][wc] = wv.y;
        __syncthreads();
#pragma unroll
        for (int k = 0; k < 8; ++k) {
            ulonglong2 a01 = *(const ulonglong2*)&As[k][tr*8];     // row pairs (0,1),(2,3)
            ulonglong2 a23 = *(const ulonglong2*)&As[k][tr*8+4];   // (4,5),(6,7)
            float4 b4 = *(const float4*)&Bs[k][tc*4];
            ull bd0 = pk2(b4.x, b4.x), bd1 = pk2(b4.y, b4.y);
            ull bd2 = pk2(b4.z, b4.z), bd3 = pk2(b4.w, b4.w);
            acc2[0][0]=ffma2(a01.x,bd0,acc2[0][0]); acc2[0][1]=ffma2(a01.x,bd1,acc2[0][1]);
            acc2[0][2]=ffma2(a01.x,bd2,acc2[0][2]); acc2[0][3]=ffma2(a01.x,bd3,acc2[0][3]);
            acc2[1][0]=ffma2(a01.y,bd0,acc2[1][0]); acc2[1][1]=ffma2(a01.y,bd1,acc2[1][1]);
            acc2[1][2]=ffma2(a01.y,bd2,acc2[1][2]); acc2[1][3]=ffma2(a01.y,bd3,acc2[1][3]);
            acc2[2][0]=ffma2(a23.x,bd0,acc2[2][0]); acc2[2][1]=ffma2(a23.x,bd1,acc2[2][1]);
            acc2[2][2]=ffma2(a23.x,bd2,acc2[2][2]); acc2[2][3]=ffma2(a23.x,bd3,acc2[2][3]);
            acc2[3][0]=ffma2(a23.y,bd0,acc2[3][0]); acc2[3][1]=ffma2(a23.y,bd1,acc2[3][1]);
            acc2[3][2]=ffma2(a23.y,bd2,acc2[3][2]); acc2[3][3]=ffma2(a23.y,bd3,acc2[3][3]);
        }
        __syncthreads();
    }
#pragma unroll
    for (int p = 0; p < 4; p++) {
        int r0 = row0 + tr * 8 + 2 * p;
#pragma unroll
        for (int j = 0; j < 4; j++) {
            int c = col0 + tc * 4 + j;
            float lo, hi; upk2(acc2[p][j], lo, hi);
            float bv = bias[c];
            C[(size_t)r0 * G4_ + c]       = lo + bv;
            C[(size_t)(r0+1) * G4_ + c]   = hi + bv;
        }
    }
}

// ---------------- persistent BiLSTM layer ----------------
// grid 128 (dir = blk/64), block 256, dyn smem 66048B.
// block owns 4 hidden units x 32 batches; 8-warp split-K FFMA2 GEMM of h @ Whh^T.
// Cheap grid barrier: bar.sync -> thread0 red.release.gpu -> thread0 ld.acquire poll -> bar.sync.
__global__ void __launch_bounds__(256, 1)
lstm_layer(const float* __restrict__ pre_f, const float* __restrict__ pre_b,
           const float* __restrict__ Whh_f, const float* __restrict__ Whh_b,
           const int* __restrict__ lengths, float* __restrict__ xcat,
           int* __restrict__ bar, float* __restrict__ hbase) {
    extern __shared__ float sm[];
    float* w_sh = sm;                 // [256][16]  (k-major)           4096 f
    float* h_sh = sm + 4096;          // [256][32]  (unit-major)        8192 f
    float* red  = sm + 12288;         // ull [8][256] partials          4096 f
    float* c_sh = sm + 16384;         // [128]                           128 f
    ull* red_u  = (ull*)red;

    int tid = threadIdx.x;
    int dir = blockIdx.x >> 6;
    int blk = blockIdx.x & 63;
    int u_base = blk * 4;
    const float* pre = dir ? pre_b : pre_f;
    const float* Whh = dir ? Whh_b : Whh_f;

    // load weight slice: rows r = gate*4+ui -> global row gate*256 + u_base + ui
    for (int idx = tid; idx < 16 * 256; idx += 256) {
        int r = idx >> 8, k = idx & 255;
        int gate = r >> 2, ui = r & 3;
        w_sh[k * 16 + r] = Whh[(size_t)(gate * 256 + u_base + ui) * 256 + k];
    }

    int warp = tid >> 5, lane = tid & 31;
    int li = lane >> 2, lj = lane & 3;     // gemm: batches 4*li.., row-group lj
    int kbase = warp * 32;
    // reducer/updater mapping: (batch bb, slot x); active threads x<4 handle unit u=x
    int x  = lane & 7;
    int u  = x & 3;
    int half = u >> 1;
    int lb = lane & ~7;                    // batch-group base lane
    int bb = tid >> 3;                     // batch 0..31
    int sel = u & 1;                       // which half of the packed pair
    int active = (x < 4);
    int cid = bb * 4 + u;
    int* bar_dir = bar + dir * T_;

    if (active) c_sh[cid] = 0.f;

    // prefetch pre-gates + length (register pipeline)
    float pg0 = 0, pg1 = 0, pg2 = 0, pg3 = 0;
    float pgn0 = 0, pgn1 = 0, pgn2 = 0, pgn3 = 0;
    int len = 0;
    if (active) {
        len = lengths[bb];
        int t0 = dir ? (T_ - 1) : 0;
        const float* pp = pre + ((size_t)t0 * B_ + bb) * G4_ + u_base + u;
        pg0 = __ldg(pp); pg1 = __ldg(pp + 256); pg2 = __ldg(pp + 512); pg3 = __ldg(pp + 768);
    }
    __syncthreads();   // w_sh / c_sh ready

    int cur = 0;
    for (int s = 0; s < T_; ++s) {
        int t = dir ? (T_ - 1 - s) : s;

        // per-warp h slice load (warp consumes k in [kbase, kbase+32))
        {
            const float* hsrc = hbase + (cur * 2 + dir) * (H_ * B_) + kbase * 32;
            float* hdst = h_sh + kbase * 32;
#pragma unroll
            for (int i = 0; i < 8; ++i) {
                int off = (lane + i * 32) * 4;
                float4 v = __ldcg((const float4*)(hsrc + off));
                *(float4*)(hdst + off) = v;
            }
            __syncwarp();
        }

        // split-K FFMA2 GEMM: warp handles k in [kbase, kbase+32)
        ull acc2[4][2];   // [batch i][row-pair jp]
#pragma unroll
        for (int i = 0; i < 4; i++) { acc2[i][0] = 0ull; acc2[i][1] = 0ull; }
#pragma unroll 8
        for (int kk = 0; kk < 32; ++kk) {
            int k = kbase + kk;
            float4 hv = *(const float4*)(h_sh + k * 32 + li * 4);
            ulonglong2 wp = *(const ulonglong2*)(w_sh + k * 16 + lj * 4);
            ull hd0 = pk2(hv.x, hv.x), hd1 = pk2(hv.y, hv.y);
            ull hd2 = pk2(hv.z, hv.z), hd3 = pk2(hv.w, hv.w);
            acc2[0][0]=ffma2(hd0,wp.x,acc2[0][0]); acc2[0][1]=ffma2(hd0,wp.y,acc2[0][1]);
            acc2[1][0]=ffma2(hd1,wp.x,acc2[1][0]); acc2[1][1]=ffma2(hd1,wp.y,acc2[1][1]);
            acc2[2][0]=ffma2(hd2,wp.x,acc2[2][0]); acc2[2][1]=ffma2(hd2,wp.y,acc2[2][1]);
            acc2[3][0]=ffma2(hd3,wp.x,acc2[3][0]); acc2[3][1]=ffma2(hd3,wp.y,acc2[3][1]);
        }
        {
            ull* rpu = red_u + warp * 256;
#pragma unroll
            for (int i = 0; i < 4; i++) {
                *(ulonglong2*)(rpu + (li * 4 + i) * 8 + lj * 2) =
                    make_ulonglong2(acc2[i][0], acc2[i][1]);
            }
        }
        __syncthreads();   // (A) partials visible

        // cross-warp reduce: thread tid owns (batch=tid>>3, row-pair rp=tid&7)
        ull sacc = red_u[tid];
#pragma unroll
        for (int w = 1; w < 8; ++w) sacc = add2(sacc, red_u[w * 256 + tid]);

        // redistribute gates within the 8-lane batch group:
        // unit u needs rows u, 4+u, 8+u, 12+u  -> row-pairs half, 2+half, 4+half, 6+half
        ull vi = __shfl_sync(0xffffffffu, sacc, lb + 0 + half);
        ull vf = __shfl_sync(0xffffffffu, sacc, lb + 2 + half);
        ull vg = __shfl_sync(0xffffffffu, sacc, lb + 4 + half);
        ull vo = __shfl_sync(0xffffffffu, sacc, lb + 6 + half);

        if (active) {
            float lo, hi, gi, gf, gg, go;
            upk2(vi, lo, hi); gi = (sel ? hi : lo) + pg0;
            upk2(vf, lo, hi); gf = (sel ? hi : lo) + pg1;
            upk2(vg, lo, hi); gg = (sel ? hi : lo) + pg2;
            upk2(vo, lo, hi); go = (sel ? hi : lo) + pg3;
            float c  = c_sh[cid];
            float si = 1.f / (1.f + __expf(-gi));
            float sf = 1.f / (1.f + __expf(-gf));
            float so = 1.f / (1.f + __expf(-go));
            float c2 = sf * c + si * tanhf(gg);
            float h2 = so * tanhf(c2);
            float hold = h_sh[(u_base + u) * 32 + bb];
            int mvalid = (t < len);
            float hw, ow;
            if (mvalid) { c_sh[cid] = c2; hw = h2; ow = h2; }
            else        { hw = hold; ow = 0.f; }
            hbase[((cur ^ 1) * 2 + dir) * (H_ * B_) + (u_base + u) * 32 + bb] = hw;
            xcat[((size_t)t * B_ + bb) * 512 + dir * 256 + u_base + u] = ow;

            // prefetch next step's pre-gates
            if (s + 1 < T_) {
                int tn = dir ? (T_ - 2 - s) : (s + 1);
                const float* pp = pre + ((size_t)tn * B_ + bb) * G4_ + u_base + u;
                pgn0 = __ldg(pp); pgn1 = __ldg(pp + 256);
                pgn2 = __ldg(pp + 512); pgn3 = __ldg(pp + 768);
            }
        }

        // per-direction grid barrier (skip after last step)
        if (s + 1 < T_) {
            __syncthreads();   // (C) all h stores issued, cta-ordered before arrive
            if (tid == 0) {
                int* p = bar_dir + s;
                asm volatile("red.release.gpu.global.add.s32 [%0], 1;" :: "l"(p) : "memory");
                int v;
                do {
                    asm volatile("ld.acquire.gpu.global.s32 %0, [%1];" : "=r"(v) : "l"(p) : "memory");
                } while (v < 64);
            }
            __syncthreads();   // (D) release the block
        }
        pg0 = pgn0; pg1 = pgn1; pg2 = pgn2; pg3 = pgn3;
        cur ^= 1;
    }
}

// ---------------- emit: (8192x512) @ Wout^T(48x512) + bout ----------------
// grid 256, block 256. Also writes transposed output emit (B,T,K).
__global__ void emit_kernel(const float* __restrict__ xcat, const float* __restrict__ Wout,
                            const float* __restrict__ bout, float* __restrict__ emit,
                            float* __restrict__ out_emit) {
    int tid = threadIdx.x;
    int r = tid & 31;
    int cg = tid >> 5;                 // 8 groups x 6 cols
    int m = blockIdx.x * 32 + r;
    int t = m >> 5, b = m & 31;
    const ulonglong2* A = (const ulonglong2*)(xcat + (size_t)m * 512);
    ull accA[6], accB[6];
#pragma unroll
    for (int j = 0; j < 6; ++j) { accA[j] = 0ull; accB[j] = 0ull; }
    for (int k4 = 0; k4 < 128; ++k4) {
        ulonglong2 a = A[k4];
#pragma unroll
        for (int j = 0; j < 6; ++j) {
            int col = cg * 6 + j;
            ulonglong2 w = ((const ulonglong2*)(Wout + (size_t)col * 512))[k4];
            accA[j] = ffma2(a.x, w.x, accA[j]);
            accB[j] = ffma2(a.y, w.y, accB[j]);
        }
    }
#pragma unroll
    for (int j = 0; j < 6; ++j) {
        int col = cg * 6 + j;
        float a0, a1, b0, b1;
        upk2(accA[j], a0, a1); upk2(accB[j], b0, b1);
        float v = a0 + a1 + b0 + b1 + bout[col];
        emit[(size_t)m * K_ + col] = v;
        out_emit[((size_t)b * T_ + t) * K_ + col] = v;
    }
}

// ---------------- CRF per batch: numerator + forward algorithm ----------------
// 192 threads: 4-way split over the j (previous-tag) dimension.
__global__ void crf_kernel(const float* __restrict__ emit, const int* __restrict__ tags,
                           const int* __restrict__ lengths, const float* __restrict__ start_t,
                           const float* __restrict__ end_t, const float* __restrict__ trans,
                           float* __restrict__ part) {
    __shared__ float tr_sh[K_ * K_];
    __shared__ float sc[K_];
    __shared__ float pmax[4][K_];
    __shared__ float psum[4][K_];
    __shared__ float redn[192];
    int b = blockIdx.x, tid = threadIdx.x;
    int k = tid % K_, jj = tid / K_;     // jj in 0..3
    for (int i = tid; i < K_ * K_; i += 192) tr_sh[i] = trans[i];
    int len = lengths[b];
    if (tid < K_) sc[tid] = start_t[tid] + emit[(size_t)b * K_ + tid];
    __syncthreads();
    for (int t = 1; t < len; ++t) {
        float v[12];
        float mx = -1e30f;
#pragma unroll
        for (int jx = 0; jx < 12; ++jx) {
            int j = jj * 12 + jx;
            v[jx] = sc[j] + tr_sh[j * K_ + k];
            mx = fmaxf(mx, v[jx]);
        }
        float ss = 0.f;
#pragma unroll
        for (int jx = 0; jx < 12; ++jx) ss += __expf(v[jx] - mx);
        pmax[jj][k] = mx; psum[jj][k] = ss;
        __syncthreads();
        if (jj == 0) {
            float m0 = pmax[0][k], m1 = pmax[1][k], m2 = pmax[2][k], m3 = pmax[3][k];
            float gm = fmaxf(fmaxf(m0, m1), fmaxf(m2, m3));
            float s = psum[0][k] * __expf(m0 - gm) + psum[1][k] * __expf(m1 - gm)
                    + psum[2][k] * __expf(m2 - gm) + psum[3][k] * __expf(m3 - gm);
            sc[k] = gm + __logf(s) + emit[((size_t)t * B_ + b) * K_ + k];
        }
        __syncthreads();
    }
    // numerator (pure sum over t, parallel)
    float np = 0.f;
    for (int t = tid; t < len; t += 192) {
        int tg = tags[b * T_ + t];
        float e = emit[((size_t)t * B_ + b) * K_ + tg];
        if (t == 0) np += start_t[tg] + e;
        else        np += tr_sh[tags[b * T_ + t - 1] * K_ + tg] + e;
        if (t == len - 1) np += end_t[tg];
    }
    redn[tid] = np;
    __syncthreads();
    if (tid == 0) {
        float num = 0.f;
        for (int i = 0; i < 192; ++i) num += redn[i];
        float mx = -1e30f;
        for (int kk = 0; kk < K_; ++kk) mx = fmaxf(mx, sc[kk] + end_t[kk]);
        float ss = 0.f;
        for (int kk = 0; kk < K_; ++kk) ss += __expf(sc[kk] + end_t[kk] - mx);
        float den = mx + __logf(ss);
        part[b] = num - den;
    }
}

__global__ void finalize_kernel(float* __restrict__ out_loss) {
    if (threadIdx.x == 0) {
        float s = 0.f;
        for (int i = 0; i < B_; ++i) s += g_part[i];
        out_loss[0] = s / (float)B_;
    }
}

// ---------------- host launcher ----------------
extern "C" void kernel_launch(void* const* d_in, const int* in_sizes, int n_in,
                              void* d_out, int out_size) {
    const int*   sentence = (const int*)d_in[0];
    const int*   lengths  = (const int*)d_in[1];
    const int*   tags     = (const int*)d_in[2];
    const float* embed    = (const float*)d_in[3];
    const float* Wih_0f = (const float*)d_in[4];
    const float* Whh_0f = (const float*)d_in[5];
    const float* b_0f   = (const float*)d_in[6];
    const float* Wih_0b = (const float*)d_in[7];
    const float* Whh_0b = (const float*)d_in[8];
    const float* b_0b   = (const float*)d_in[9];
    const float* Wih_1f = (const float*)d_in[10];
    const float* Whh_1f = (const float*)d_in[11];
    const float* b_1f   = (const float*)d_in[12];
    const float* Wih_1b = (const float*)d_in[13];
    const float* Whh_1b = (const float*)d_in[14];
    const float* b_1b   = (const float*)d_in[15];
    const float* Wout   = (const float*)d_in[16];
    const float* bout   = (const float*)d_in[17];
    const float* start_t = (const float*)d_in[18];
    const float* end_t   = (const float*)d_in[19];
    const float* trans   = (const float*)d_in[20];

    float* out = (float*)d_out;
    float* out_emit = out;                       // (B,T,K) = 393216
    float* out_loss = out + (size_t)B_ * T_ * K_;
    float* out_mask = out_loss + 1;              // (B,T)

    const int LSTM_SMEM = 16512 * 4;             // 66048 B
    cudaFuncSetAttribute(lstm_layer, cudaFuncAttributeMaxDynamicSharedMemorySize, LSTM_SMEM);

    float *pre_f, *pre_b, *xcat, *emb, *emit, *hbase;
    cudaGetSymbolAddress((void**)&pre_f, g_pref);
    cudaGetSymbolAddress((void**)&pre_b, g_preb);
    cudaGetSymbolAddress((void**)&xcat,  g_xcat);
    cudaGetSymbolAddress((void**)&emb,   g_emb);
    cudaGetSymbolAddress((void**)&emit,  g_emit);
    cudaGetSymbolAddress((void**)&hbase, g_h);
    int* barp; cudaGetSymbolAddress((void**)&barp, g_bar);
    float* partp; cudaGetSymbolAddress((void**)&partp, g_part);

    dim3 ggrid(16, 64, 2);

    init_kernel<<<32, 256>>>();
    embed_kernel<<<M_, 64>>>(sentence, embed, out_mask);

    gemm_pre<<<ggrid, 256>>>(emb, Wih_0f, Wih_0b, b_0f, b_0b, pre_f, pre_b, E_);
    lstm_layer<<<128, 256, LSTM_SMEM>>>(pre_f, pre_b, Whh_0f, Whh_0b, lengths, xcat,
                                        barp, hbase);

    gemm_pre<<<ggrid, 256>>>(xcat, Wih_1f, Wih_1b, b_1f, b_1b, pre_f, pre_b, 512);
    lstm_layer<<<128, 256, LSTM_SMEM>>>(pre_f, pre_b, Whh_1f, Whh_1b, lengths, xcat,
                                        barp + 2 * T_, hbase + 2 * 2 * H_ * B_);

    emit_kernel<<<M_ / 32, 256>>>(xcat, Wout, bout, emit, out_emit);
    crf_kernel<<<B_, 192>>>(emit, tags, lengths, start_t, end_t, trans, partp);
    finalize_kernel<<<1, 32>>>(out_loss);
    (void)in_sizes; (void)n_in; (void)out_size;
}